// round 6
// baseline (speedup 1.0000x reference)
#include <cuda_runtime.h>

#define NQ 13

// Transfer-matrix contraction (bond dim 4, Hermitian-reduced to 4 reals).
// ev[q] = <0| G1+ C+ G2+ (prefix-Z over wires 0..q) G2 C G1 |0>
// Layer-2 M_w = U2_w+ Z U2_w: the RZ factor of U2 cancels (Z commutes with
// diagonal phases), giving closed form with FULL angles t1=x*w0, t2=x*w1:
//   m  = cos t1 * cos t2
//   mu = -sin t2 - i sin t1 cos t2        (M = [[m, mu],[mu*, -m]])
// Layer-1 phi = first column of RZ*RY*RX (half angles; relative phase needed).
// CNOT chain = Gray perm -> nearest-neighbor coupling; identity tail
// telescopes to boundary factor kappa_{q+1} = 2 Re(conj(phi0) phi1).
__global__ void qsim_tn(const float* __restrict__ x,
                        const float* __restrict__ wts,
                        float* __restrict__ out,
                        int n)
{
    const int e = blockIdx.x * blockDim.x + threadIdx.x;
    if (e >= n) return;

    // front-batch the 13 input loads (MLP)
    float xr[NQ];
    #pragma unroll
    for (int q = 0; q < NQ; q++) xr[q] = __ldg(&x[e * NQ + q]);

    float v00 = 0.f, v11 = 0.f, v01x = 0.f, v01y = 0.f;

    #pragma unroll
    for (int q = 0; q < NQ; q++) {
        const float xv = xr[q];

        // ---- layer-1 phi (half angles, RZ relative phase kept) ----
        float s1, c1, s2, c2, sp, cp;
        __sincosf(0.5f * xv * __ldg(&wts[q * 3 + 0]), &s1, &c1);
        __sincosf(0.5f * xv * __ldg(&wts[q * 3 + 1]), &s2, &c2);
        __sincosf(0.5f * __ldg(&wts[q * 3 + 2]),      &sp, &cp);
        const float A = c2 * c1, B = s2 * s1, C = s2 * c1, D = c2 * s1;
        const float p0x = fmaf(cp, A,  sp * B);
        const float p0y = fmaf(cp, B, -sp * A);
        const float p1x = fmaf(cp, C,  sp * D);
        const float p1y = fmaf(sp, C, -cp * D);
        const float kap = 2.f * fmaf(p0x, p1x, p0y * p1y);

        // ---- emit ev[q-1]: v after wire q-1, boundary kappa of wire q ----
        if (q > 0)
            out[e * NQ + (q - 1)] = v00 + v11 + kap * (2.f * v01x);

        // ---- layer-2 M in closed form (full angles; RZ cancels) ----
        float sa, ca, sb, cb;
        __sincosf(xv * __ldg(&wts[(NQ + q) * 3 + 0]), &sa, &ca);
        __sincosf(xv * __ldg(&wts[(NQ + q) * 3 + 1]), &sb, &cb);
        const float m   = ca * cb;
        const float mux = -sb;
        const float muy = -sa * cb;

        if (q == 0) {
            // v(a,a') = conj(phi(a)) M(a,a') phi(a')
            v00  =  m * fmaf(p0x, p0x, p0y * p0y);
            v11  = -m * fmaf(p1x, p1x, p1y * p1y);
            const float tx = fmaf(p0x, p1x,  p0y * p1y);   // conj(p0)*p1
            const float ty = fmaf(p0x, p1y, -p0y * p1x);
            v01x = fmaf(mux, tx, -muy * ty);
            v01y = fmaf(mux, ty,  muy * tx);
        } else {
            // h(c,a') = sum_{c'} phi(a'^c') v(c,c')
            const float h00x = fmaf(p0x, v00, fmaf(p1x, v01x, -p1y * v01y));
            const float h00y = fmaf(p0y, v00, fmaf(p1x, v01y,  p1y * v01x));
            const float h01x = fmaf(p1x, v00, fmaf(p0x, v01x, -p0y * v01y));
            const float h01y = fmaf(p1y, v00, fmaf(p0x, v01y,  p0y * v01x));
            const float h10x = fmaf(p1x, v11, fmaf(p0x, v01x,  p0y * v01y));
            const float h10y = fmaf(p1y, v11, fmaf(p0y, v01x, -p0x * v01y));
            const float h11x = fmaf(p0x, v11, fmaf(p1x, v01x,  p1y * v01y));
            const float h11y = fmaf(p0y, v11, fmaf(p1y, v01x, -p1x * v01y));
            // w(a,a') = sum_c conj(phi(a^c)) h(c,a')
            const float w00  = fmaf(p0x, h00x, p0y * h00y) + fmaf(p1x, h10x, p1y * h10y);
            const float w01x = fmaf(p0x, h01x, p0y * h01y) + fmaf(p1x, h11x, p1y * h11y);
            const float w01y = fmaf(p0x, h01y, -p0y * h01x) + fmaf(p1x, h11y, -p1y * h11x);
            const float w11  = fmaf(p1x, h01x, p1y * h01y) + fmaf(p0x, h11x, p0y * h11y);
            // v_new = M .* w
            v00  =  m * w00;
            v11  = -m * w11;
            v01x = fmaf(mux, w01x, -muy * w01y);
            v01y = fmaf(mux, w01y,  muy * w01x);
        }
    }

    out[e * NQ + (NQ - 1)] = v00 + v11 + 2.f * v01x;
}

extern "C" void kernel_launch(void* const* d_in, const int* in_sizes, int n_in,
                              void* d_out, int out_size)
{
    const float* x = (const float*)d_in[0];   // (B, 13) float32
    const float* w = (const float*)d_in[1];   // (2, 13, 3) float32
    float* out     = (float*)d_out;           // (B, 13) float32

    const int B = in_sizes[0] / NQ;           // 512
    const int TPB = 32;
    const int grid = (B + TPB - 1) / TPB;     // 16 warps across 16 SMs
    qsim_tn<<<grid, TPB>>>(x, w, out, B);
}

// round 7
// speedup vs baseline: 1.2917x; 1.2917x over previous
#include <cuda_runtime.h>

#define NQ 13
#define FULL 0xffffffffu

// Transfer-matrix contraction (bond dim 4, Hermitian-reduced).
// One warp per batch element:
//   - lane q (q<13) computes wire q's gate parameters (all trig in parallel)
//   - all lanes redundantly run the 13-step sequential chain, pulling lane
//     q's params via __shfl_sync (immediate lane index)
//   - ev[q] is kept by lane q -> single coalesced store at the end.
// Math identical to R6:
//   layer-2 M = U2+ Z U2 with RZ cancelled:
//     m = cos t1 cos t2,  mu = -sin t2 - i sin t1 cos t2  (full angles)
//   layer-1 phi = first column of RZ*RY*RX (half angles)
//   CNOT chain = Gray perm -> nearest-neighbor coupling; identity tail
//   telescopes to boundary factor kappa_{q+1} = 2 Re(conj(phi0) phi1).
__global__ void qsim_tn(const float* __restrict__ x,
                        const float* __restrict__ wts,
                        float* __restrict__ out,
                        int n)
{
    const int e = blockIdx.x;
    if (e >= n) return;
    const int l = threadIdx.x;          // lane 0..31

    // ---- per-lane gate parameters for wire l (lanes 13..31 idle) ----
    float p0x = 0.f, p0y = 0.f, p1x = 0.f, p1y = 0.f;
    float kap = 0.f, m = 0.f, mux = 0.f, muy = 0.f;
    if (l < NQ) {
        const float xv = __ldg(&x[e * NQ + l]);
        float s1, c1, s2, c2, sp, cp;
        __sincosf(0.5f * xv * __ldg(&wts[l * 3 + 0]), &s1, &c1);   // RX half
        __sincosf(0.5f * xv * __ldg(&wts[l * 3 + 1]), &s2, &c2);   // RY half
        __sincosf(0.5f * __ldg(&wts[l * 3 + 2]),      &sp, &cp);   // RZ half
        const float A = c2 * c1, B = s2 * s1, C = s2 * c1, D = c2 * s1;
        p0x = fmaf(cp, A,  sp * B);
        p0y = fmaf(cp, B, -sp * A);
        p1x = fmaf(cp, C,  sp * D);
        p1y = fmaf(sp, C, -cp * D);
        kap = 2.f * fmaf(p0x, p1x, p0y * p1y);

        float sa, ca, sb, cb;
        __sincosf(xv * __ldg(&wts[(NQ + l) * 3 + 0]), &sa, &ca);   // full angles
        __sincosf(xv * __ldg(&wts[(NQ + l) * 3 + 1]), &sb, &cb);
        m   = ca * cb;
        mux = -sb;
        muy = -sa * cb;
    }

    // ---- sequential chain, run by all lanes; params broadcast per step ----
    float v00 = 0.f, v11 = 0.f, v01x = 0.f, v01y = 0.f;
    float my_ev = 0.f;

    #pragma unroll
    for (int q = 0; q < NQ; q++) {
        const float g0x = __shfl_sync(FULL, p0x, q);
        const float g0y = __shfl_sync(FULL, p0y, q);
        const float g1x = __shfl_sync(FULL, p1x, q);
        const float g1y = __shfl_sync(FULL, p1y, q);
        const float gk  = __shfl_sync(FULL, kap, q);
        const float gm  = __shfl_sync(FULL, m,   q);
        const float gux = __shfl_sync(FULL, mux, q);
        const float guy = __shfl_sync(FULL, muy, q);

        if (q > 0) {
            const float ev = v00 + v11 + gk * (2.f * v01x);
            if (l == q - 1) my_ev = ev;
        }

        if (q == 0) {
            v00  =  gm * fmaf(g0x, g0x, g0y * g0y);
            v11  = -gm * fmaf(g1x, g1x, g1y * g1y);
            const float tx = fmaf(g0x, g1x,  g0y * g1y);   // conj(p0)*p1
            const float ty = fmaf(g0x, g1y, -g0y * g1x);
            v01x = fmaf(gux, tx, -guy * ty);
            v01y = fmaf(gux, ty,  guy * tx);
        } else {
            // h(c,a') = sum_{c'} phi(a'^c') v(c,c')
            const float h00x = fmaf(g0x, v00, fmaf(g1x, v01x, -g1y * v01y));
            const float h00y = fmaf(g0y, v00, fmaf(g1x, v01y,  g1y * v01x));
            const float h01x = fmaf(g1x, v00, fmaf(g0x, v01x, -g0y * v01y));
            const float h01y = fmaf(g1y, v00, fmaf(g0x, v01y,  g0y * v01x));
            const float h10x = fmaf(g1x, v11, fmaf(g0x, v01x,  g0y * v01y));
            const float h10y = fmaf(g1y, v11, fmaf(g0y, v01x, -g0x * v01y));
            const float h11x = fmaf(g0x, v11, fmaf(g1x, v01x,  g1y * v01y));
            const float h11y = fmaf(g0y, v11, fmaf(g1y, v01x, -g1x * v01y));
            // w(a,a') = sum_c conj(phi(a^c)) h(c,a')
            const float w00  = fmaf(g0x, h00x, g0y * h00y) + fmaf(g1x, h10x, g1y * h10y);
            const float w01x = fmaf(g0x, h01x, g0y * h01y) + fmaf(g1x, h11x, g1y * h11y);
            const float w01y = fmaf(g0x, h01y, -g0y * h01x) + fmaf(g1x, h11y, -g1y * h11x);
            const float w11  = fmaf(g1x, h01x, g1y * h01y) + fmaf(g0x, h11x, g0y * h11y);
            v00  =  gm * w00;
            v11  = -gm * w11;
            v01x = fmaf(gux, w01x, -guy * w01y);
            v01y = fmaf(gux, w01y,  guy * w01x);
        }
    }

    {
        const float ev = v00 + v11 + 2.f * v01x;
        if (l == NQ - 1) my_ev = ev;
    }

    if (l < NQ) out[e * NQ + l] = my_ev;
}

extern "C" void kernel_launch(void* const* d_in, const int* in_sizes, int n_in,
                              void* d_out, int out_size)
{
    const float* x = (const float*)d_in[0];   // (B, 13) float32
    const float* w = (const float*)d_in[1];   // (2, 13, 3) float32
    float* out     = (float*)d_out;           // (B, 13) float32

    const int B = in_sizes[0] / NQ;           // 512
    qsim_tn<<<B, 32>>>(x, w, out, B);         // one warp per element
}

// round 8
// speedup vs baseline: 1.3413x; 1.0385x over previous
#include <cuda_runtime.h>

#define NQ 13
#define FULL 0xffffffffu

// Transfer-matrix contraction (bond dim 4, Hermitian-reduced).
// One warp per batch element, 8 warps per CTA.
//   - lanes 0..12:  layer-1 params (phi, kappa) for wire l   (3 sincosf)
//   - lanes 16..28: layer-2 params (m, mu) for wire l-16      (2 sincosf)
//   - all lanes redundantly run the 13-step chain, pulling params via shfl
//   - ev[q] kept by lane q -> one coalesced store.
// Math (verified R5-R7):
//   layer-2 M = U2+ Z U2, RZ cancels:  m = cos t1 cos t2,
//     mu = -sin t2 - i sin t1 cos t2   (FULL angles t = x*w)
//   layer-1 phi = first column of RZ*RY*RX (half angles)
//   CNOT chain = Gray perm -> nearest-neighbor transfer chain; identity tail
//   telescopes to boundary factor kappa_{q+1} = 2 Re(conj(phi0) phi1).
__global__ __launch_bounds__(256)
void qsim_tn(const float* __restrict__ x,
             const float* __restrict__ wts,
             float* __restrict__ out,
             int n)
{
    const int e = blockIdx.x * 8 + (threadIdx.x >> 5);
    const int l = threadIdx.x & 31;
    if (e >= n) return;

    // ---- per-lane gate parameters ----
    float p0x = 0.f, p0y = 0.f, p1x = 0.f, p1y = 0.f, kap = 0.f;
    float m = 0.f, mux = 0.f, muy = 0.f;

    if (l < NQ) {
        // layer-1 wire l
        const float xv = __ldg(&x[e * NQ + l]);
        const float w0 = __ldg(&wts[l * 3 + 0]);
        const float w1 = __ldg(&wts[l * 3 + 1]);
        const float w2 = __ldg(&wts[l * 3 + 2]);
        float s1, c1, s2, c2, sp, cp;
        __sincosf(0.5f * xv * w0, &s1, &c1);   // RX half
        __sincosf(0.5f * xv * w1, &s2, &c2);   // RY half
        __sincosf(0.5f * w2,      &sp, &cp);   // RZ half
        const float A = c2 * c1, B = s2 * s1, C = s2 * c1, D = c2 * s1;
        p0x = fmaf(cp, A,  sp * B);
        p0y = fmaf(cp, B, -sp * A);
        p1x = fmaf(cp, C,  sp * D);
        p1y = fmaf(sp, C, -cp * D);
        kap = 2.f * fmaf(p0x, p1x, p0y * p1y);
    } else if (l >= 16 && l < 16 + NQ) {
        // layer-2 wire (l-16)
        const int q = l - 16;
        const float xv = __ldg(&x[e * NQ + q]);
        const float w0 = __ldg(&wts[(NQ + q) * 3 + 0]);
        const float w1 = __ldg(&wts[(NQ + q) * 3 + 1]);
        float sa, ca, sb, cb;
        __sincosf(xv * w0, &sa, &ca);          // full angles
        __sincosf(xv * w1, &sb, &cb);
        m   = ca * cb;
        mux = -sb;
        muy = -sa * cb;
    }

    // ---- sequential chain, all lanes; params broadcast per step ----
    float v00 = 0.f, v11 = 0.f, v01x = 0.f, v01y = 0.f;
    float my_ev = 0.f;

    #pragma unroll
    for (int q = 0; q < NQ; q++) {
        const float g0x = __shfl_sync(FULL, p0x, q);
        const float g0y = __shfl_sync(FULL, p0y, q);
        const float g1x = __shfl_sync(FULL, p1x, q);
        const float g1y = __shfl_sync(FULL, p1y, q);
        const float gk  = __shfl_sync(FULL, kap, q);
        const float gm  = __shfl_sync(FULL, m,   16 + q);
        const float gux = __shfl_sync(FULL, mux, 16 + q);
        const float guy = __shfl_sync(FULL, muy, 16 + q);

        if (q > 0) {
            const float ev = v00 + v11 + gk * (2.f * v01x);
            if (l == q - 1) my_ev = ev;
        }

        if (q == 0) {
            v00  =  gm * fmaf(g0x, g0x, g0y * g0y);
            v11  = -gm * fmaf(g1x, g1x, g1y * g1y);
            const float tx = fmaf(g0x, g1x,  g0y * g1y);   // conj(p0)*p1
            const float ty = fmaf(g0x, g1y, -g0y * g1x);
            v01x = fmaf(gux, tx, -guy * ty);
            v01y = fmaf(gux, ty,  guy * tx);
        } else {
            // h(c,a') = sum_{c'} phi(a'^c') v(c,c')
            const float h00x = fmaf(g0x, v00, fmaf(g1x, v01x, -g1y * v01y));
            const float h00y = fmaf(g0y, v00, fmaf(g1x, v01y,  g1y * v01x));
            const float h01x = fmaf(g1x, v00, fmaf(g0x, v01x, -g0y * v01y));
            const float h01y = fmaf(g1y, v00, fmaf(g0x, v01y,  g0y * v01x));
            const float h10x = fmaf(g1x, v11, fmaf(g0x, v01x,  g0y * v01y));
            const float h10y = fmaf(g1y, v11, fmaf(g0y, v01x, -g0x * v01y));
            const float h11x = fmaf(g0x, v11, fmaf(g1x, v01x,  g1y * v01y));
            const float h11y = fmaf(g0y, v11, fmaf(g1y, v01x, -g1x * v01y));
            // w(a,a') = sum_c conj(phi(a^c)) h(c,a')
            const float w00  = fmaf(g0x, h00x, g0y * h00y) + fmaf(g1x, h10x, g1y * h10y);
            const float w01x = fmaf(g0x, h01x, g0y * h01y) + fmaf(g1x, h11x, g1y * h11y);
            const float w01y = fmaf(g0x, h01y, -g0y * h01x) + fmaf(g1x, h11y, -g1y * h11x);
            const float w11  = fmaf(g1x, h01x, g1y * h01y) + fmaf(g0x, h11x, g0y * h11y);
            v00  =  gm * w00;
            v11  = -gm * w11;
            v01x = fmaf(gux, w01x, -guy * w01y);
            v01y = fmaf(gux, w01y,  guy * w01x);
        }
    }

    {
        const float ev = v00 + v11 + 2.f * v01x;
        if (l == NQ - 1) my_ev = ev;
    }

    if (l < NQ) out[e * NQ + l] = my_ev;
}

extern "C" void kernel_launch(void* const* d_in, const int* in_sizes, int n_in,
                              void* d_out, int out_size)
{
    const float* x = (const float*)d_in[0];   // (B, 13) float32
    const float* w = (const float*)d_in[1];   // (2, 13, 3) float32
    float* out     = (float*)d_out;           // (B, 13) float32

    const int B = in_sizes[0] / NQ;           // 512
    const int blocks = (B + 7) / 8;           // 64 CTAs x 256 threads
    qsim_tn<<<blocks, 256>>>(x, w, out, B);
}